// round 10
// baseline (speedup 1.0000x reference)
#include <cuda_runtime.h>

#define NN 4096
#define DIM 64
#define INF_V 1e10f
#define NBLK 32           // 32 bands x 128 rows (one warp per band, 4 rows/lane)
#define NT2 512           // tile-columns (8 cols each)
#define LOG2E 1.4426950408889634f
#define LN2   0.6931471805599453f

// Scratch (static __device__ arrays: allocation-free per harness rules)
__device__ float g_D[(size_t)NN * NN];    // cost matrix, PRE-SCALED by log2(e)
__device__ float g_xn[NN];
__device__ float g_yn[NN];
__device__ float g_bnd[NBLK][NN];         // bottom boundary row of each band (base-2)
__device__ int   g_prog[NBLK];            // boundary columns published per band

// ---------------- norms ----------------
__global__ void norms_kernel(const float* __restrict__ x, const float* __restrict__ y) {
    int w = (blockIdx.x * blockDim.x + threadIdx.x) >> 5;
    int lane = threadIdx.x & 31;
    if (w >= 2 * NN) return;
    const float* src = (w < NN) ? x : y;
    int row = (w < NN) ? w : w - NN;
    float a = src[row * DIM + lane];
    float b = src[row * DIM + 32 + lane];
    float s = a * a + b * b;
    #pragma unroll
    for (int o = 16; o; o >>= 1) s += __shfl_xor_sync(0xffffffffu, s, o);
    if (lane == 0) { if (w < NN) g_xn[row] = s; else g_yn[row] = s; }
}

// ---------------- D2 = (|x|^2 + |y|^2 - 2 x.y) * log2(e) ----------------
__global__ void dmat_kernel(const float* __restrict__ x, const float* __restrict__ y) {
    __shared__ float xs[64][65];
    __shared__ float ys[64][65];
    int tx = threadIdx.x, ty = threadIdx.y;
    int tid = ty * 16 + tx;
    int rb = blockIdx.y * 64, cb = blockIdx.x * 64;

    for (int i = tid; i < 64 * 64; i += 256) {
        int rr = i >> 6, kk = i & 63;
        xs[rr][kk] = x[(rb + rr) * DIM + kk];
        ys[rr][kk] = y[(cb + rr) * DIM + kk];
    }
    __syncthreads();

    float acc[4][4] = {};
    #pragma unroll
    for (int k = 0; k < 64; k++) {
        float xv[4], yv[4];
        #pragma unroll
        for (int i = 0; i < 4; i++) xv[i] = xs[ty + 16 * i][k];
        #pragma unroll
        for (int j = 0; j < 4; j++) yv[j] = ys[tx + 16 * j][k];
        #pragma unroll
        for (int i = 0; i < 4; i++)
            #pragma unroll
            for (int j = 0; j < 4; j++)
                acc[i][j] += xv[i] * yv[j];
    }

    #pragma unroll
    for (int i = 0; i < 4; i++) {
        int r = rb + ty + 16 * i;
        float xnr = g_xn[r];
        #pragma unroll
        for (int j = 0; j < 4; j++) {
            int c = cb + tx + 16 * j;
            g_D[(size_t)r * NN + c] = (xnr + g_yn[c] - 2.0f * acc[i][j]) * LOG2E;
        }
    }
}

// ---------------- reset progress flags ----------------
__global__ void init_kernel() {
    if (threadIdx.x < NBLK) g_prog[threadIdx.x] = 0;
}

// ---------------- DP wavefront: 4x8 tiles in wavefront issue order ----------
__device__ __forceinline__ int ld_acq(const int* p) {
    int v;
    asm volatile("ld.acquire.gpu.u32 %0, [%1];" : "=r"(v) : "l"(p) : "memory");
    return v;
}
__device__ __forceinline__ void st_rel(int* p, int v) {
    asm volatile("st.release.gpu.u32 [%0], %1;" :: "l"(p), "r"(v) : "memory");
}
__device__ __forceinline__ float ex2(float x) {
    float r; asm("ex2.approx.f32 %0, %1;" : "=f"(r) : "f"(x)); return r;
}
__device__ __forceinline__ float lg2(float x) {
    float r; asm("lg2.approx.f32 %0, %1;" : "=f"(r) : "f"(x)); return r;
}

// base-2 softmin cell, 3 MUFU: the min's exp term is exactly 1.
#define CELL(nv, u, d, l, cost) do {                                   \
    float p_ = fminf((u), (d));                                        \
    float q_ = fmaxf((u), (d));                                        \
    float m_ = fminf(p_, (l));                                         \
    float md_ = fmaxf(p_, fminf(q_, (l)));                             \
    float mx_ = fmaxf(q_, (l));                                        \
    float s_ = 1.0f + ex2(m_ - md_) + ex2(m_ - mx_);                   \
    (nv) = (cost) + m_ - lg2(s_);                                      \
} while (0)

__global__ void __launch_bounds__(32, 1) dp_kernel(float* __restrict__ out) {
    __shared__ float tb[17];   // boundary window: cols [16g-1 .. 16g+15]

    const int b = blockIdx.x;
    const int L = threadIdx.x;
    const int row0 = b * 128 + 4 * L;
    const float4* __restrict__ Dr0 = (const float4*)(g_D + (size_t)(row0 + 0) * NN);
    const float4* __restrict__ Dr1 = (const float4*)(g_D + (size_t)(row0 + 1) * NN);
    const float4* __restrict__ Dr2 = (const float4*)(g_D + (size_t)(row0 + 2) * NN);
    const float4* __restrict__ Dr3 = (const float4*)(g_D + (size_t)(row0 + 3) * NN);
    float* mybnd = g_bnd[b];
    const float* upbnd = (b > 0) ? g_bnd[b - 1] : (const float*)0;

    float lft0 = INF_V, lft1 = INF_V, lft2 = INF_V, lft3 = INF_V; // right edge of prev tile
    float bot0 = INF_V, bot1 = INF_V, bot2 = INF_V, bot3 = INF_V; // bottom row of prev tile
    float bot4 = INF_V, bot5 = INF_V, bot6 = INF_V, bot7 = INF_V;
    float dgv = INF_V;                                             // v[row0-1][8j-1]

    // prefetch tile 0 costs (8 float4: two per row)
    float4 c00 = __ldg(Dr0 + 0), c01 = __ldg(Dr0 + 1);
    float4 c10 = __ldg(Dr1 + 0), c11 = __ldg(Dr1 + 1);
    float4 c20 = __ldg(Dr2 + 0), c21 = __ldg(Dr2 + 1);
    float4 c30 = __ldg(Dr3 + 0), c31 = __ldg(Dr3 + 1);

    const int TT = NT2 + 31;
    #pragma unroll 1
    for (int tau = 0; tau < TT; tau++) {
        const int j = tau - L;                    // this lane's tile-column

        // ---- stage boundary window every 2 tiles (16 cols) ----
        if (b > 0 && tau < NT2 && (tau & 1) == 0) {
            int g = tau >> 1;
            if (L == 0) { while (ld_acq(&g_prog[b - 1]) < 16 * g + 16) { } }
            __syncwarp();
            if (L < 17) {
                int col = 16 * g - 1 + L;
                tb[L] = (col >= 0) ? __ldcg(&upbnd[col]) : INF_V;
            }
            __syncwarp();
        }

        // ---- prefetch next tile's costs ----
        int jn = j + 1; if (jn < 0) jn = 0; if (jn > NT2 - 1) jn = NT2 - 1;
        float4 p00 = __ldg(Dr0 + 2 * jn), p01 = __ldg(Dr0 + 2 * jn + 1);
        float4 p10 = __ldg(Dr1 + 2 * jn), p11 = __ldg(Dr1 + 2 * jn + 1);
        float4 p20 = __ldg(Dr2 + 2 * jn), p21 = __ldg(Dr2 + 2 * jn + 1);
        float4 p30 = __ldg(Dr3 + 2 * jn), p31 = __ldg(Dr3 + 2 * jn + 1);

        // ---- top handoff: neighbor's bottom row from previous step ----
        float t0 = __shfl_up_sync(0xffffffffu, bot0, 1);
        float t1 = __shfl_up_sync(0xffffffffu, bot1, 1);
        float t2 = __shfl_up_sync(0xffffffffu, bot2, 1);
        float t3 = __shfl_up_sync(0xffffffffu, bot3, 1);
        float t4 = __shfl_up_sync(0xffffffffu, bot4, 1);
        float t5 = __shfl_up_sync(0xffffffffu, bot5, 1);
        float t6 = __shfl_up_sync(0xffffffffu, bot6, 1);
        float t7 = __shfl_up_sync(0xffffffffu, bot7, 1);

        if (b == 0) {
            if (L == 0) {
                t0 = t1 = t2 = t3 = t4 = t5 = t6 = t7 = INF_V;
                dgv = (tau == 0) ? 0.0f : INF_V;
            }
        } else {
            // branchless edge injection: broadcast LDS + per-lane SEL
            int p = (tau & 1) << 3;
            float w0 = tb[p + 0], w1 = tb[p + 1], w2 = tb[p + 2];
            float w3 = tb[p + 3], w4 = tb[p + 4], w5 = tb[p + 5];
            float w6 = tb[p + 6], w7 = tb[p + 7], w8 = tb[p + 8];
            bool e = (L == 0);
            dgv = e ? w0 : dgv;
            t0 = e ? w1 : t0; t1 = e ? w2 : t1; t2 = e ? w3 : t2;
            t3 = e ? w4 : t3; t4 = e ? w5 : t4; t5 = e ? w6 : t5;
            t6 = e ? w7 : t6; t7 = e ? w8 : t7;
        }
        dgv = (j == 0 && L > 0) ? INF_V : dgv;    // diag of col 0 is dp[.][-1]

        if (j >= 0 && j < NT2) {
            // 4x8 tile, cells emitted in anti-diagonal (wavefront) order.
            float V00, V01, V02, V03, V04, V05, V06, V07;
            float V10, V11, V12, V13, V14, V15, V16, V17;
            float V20, V21, V22, V23, V24, V25, V26, V27;
            float V30, V31, V32, V33, V34, V35, V36, V37;
            // rank 0
            CELL(V00, t0,  dgv,  lft0, c00.x);
            // rank 1
            CELL(V01, t1,  t0,   V00,  c00.y);
            CELL(V10, V00, lft0, lft1, c10.x);
            // rank 2
            CELL(V02, t2,  t1,   V01,  c00.z);
            CELL(V11, V01, V00,  V10,  c10.y);
            CELL(V20, V10, lft1, lft2, c20.x);
            // rank 3
            CELL(V03, t3,  t2,   V02,  c00.w);
            CELL(V12, V02, V01,  V11,  c10.z);
            CELL(V21, V11, V10,  V20,  c20.y);
            CELL(V30, V20, lft2, lft3, c30.x);
            // rank 4
            CELL(V04, t4,  t3,   V03,  c01.x);
            CELL(V13, V03, V02,  V12,  c10.w);
            CELL(V22, V12, V11,  V21,  c20.z);
            CELL(V31, V21, V20,  V30,  c30.y);
            // rank 5
            CELL(V05, t5,  t4,   V04,  c01.y);
            CELL(V14, V04, V03,  V13,  c11.x);
            CELL(V23, V13, V12,  V22,  c20.w);
            CELL(V32, V22, V21,  V31,  c30.z);
            // rank 6
            CELL(V06, t6,  t5,   V05,  c01.z);
            CELL(V15, V05, V04,  V14,  c11.y);
            CELL(V24, V14, V13,  V23,  c21.x);
            CELL(V33, V23, V22,  V32,  c30.w);
            // rank 7
            CELL(V07, t7,  t6,   V06,  c01.w);
            CELL(V16, V06, V05,  V15,  c11.z);
            CELL(V25, V15, V14,  V24,  c21.y);
            CELL(V34, V24, V23,  V33,  c31.x);
            // rank 8
            CELL(V17, V07, V06,  V16,  c11.w);
            CELL(V26, V16, V15,  V25,  c21.z);
            CELL(V35, V25, V24,  V34,  c31.y);
            // rank 9
            CELL(V27, V17, V16,  V26,  c21.w);
            CELL(V36, V26, V25,  V35,  c31.z);
            // rank 10
            CELL(V37, V27, V26,  V36,  c31.w);

            lft0 = V07; lft1 = V17; lft2 = V27; lft3 = V37;
            bot0 = V30; bot1 = V31; bot2 = V32; bot3 = V33;
            bot4 = V34; bot5 = V35; bot6 = V36; bot7 = V37;

            if (L == 31) {
                *(float4*)&mybnd[8 * j]     = make_float4(V30, V31, V32, V33);
                *(float4*)&mybnd[8 * j + 4] = make_float4(V34, V35, V36, V37);
                if ((j & 1) && b < NBLK - 1)
                    st_rel(&g_prog[b], 8 * j + 8);   // release orders mybnd stores
            }
        }
        dgv = t7;                                 // diag for next tile = top[7]

        c00 = p00; c01 = p01; c10 = p10; c11 = p11;   // rotate cost buffers
        c20 = p20; c21 = p21; c30 = p30; c31 = p31;
    }

    if (b == NBLK - 1 && L == 31) out[0] = lft3 * LN2;   // dp[4096][4096]
}

extern "C" void kernel_launch(void* const* d_in, const int* in_sizes, int n_in,
                              void* d_out, int out_size) {
    const float* x = (const float*)d_in[0];
    const float* y = (const float*)d_in[1];
    float* out = (float*)d_out;

    norms_kernel<<<(2 * NN * 32) / 256, 256>>>(x, y);
    dim3 gD(NN / 64, NN / 64);
    dim3 bD(16, 16);
    dmat_kernel<<<gD, bD>>>(x, y);
    init_kernel<<<1, NBLK>>>();
    dp_kernel<<<NBLK, 32>>>(out);
}

// round 11
// speedup vs baseline: 1.0241x; 1.0241x over previous
#include <cuda_runtime.h>

#define NN 4096
#define DIM 64
#define INF_V 1e10f
#define NBLK 32           // 32 bands x 128 rows (one warp per band, 4 rows/lane)
#define WPB 8             // 8 bands per block -> 2 warps per SMSP
#define NTILE 1024        // tile-columns (4 cols each)
#define LOG2E 1.4426950408889634f
#define LN2   0.6931471805599453f

// Scratch (static __device__ arrays: allocation-free per harness rules)
__device__ float g_D[(size_t)NN * NN];    // cost matrix, PRE-SCALED by log2(e)
__device__ float g_xn[NN];
__device__ float g_yn[NN];
__device__ float g_bnd[NBLK][NN];         // bottom boundary row of each band (base-2)
__device__ int   g_prog[NBLK];            // tiles published per band

// ---------------- norms ----------------
__global__ void norms_kernel(const float* __restrict__ x, const float* __restrict__ y) {
    int w = (blockIdx.x * blockDim.x + threadIdx.x) >> 5;
    int lane = threadIdx.x & 31;
    if (w >= 2 * NN) return;
    const float* src = (w < NN) ? x : y;
    int row = (w < NN) ? w : w - NN;
    float a = src[row * DIM + lane];
    float b = src[row * DIM + 32 + lane];
    float s = a * a + b * b;
    #pragma unroll
    for (int o = 16; o; o >>= 1) s += __shfl_xor_sync(0xffffffffu, s, o);
    if (lane == 0) { if (w < NN) g_xn[row] = s; else g_yn[row] = s; }
}

// ---------------- D2 = (|x|^2 + |y|^2 - 2 x.y) * log2(e) ----------------
__global__ void dmat_kernel(const float* __restrict__ x, const float* __restrict__ y) {
    __shared__ float xs[64][65];
    __shared__ float ys[64][65];
    int tx = threadIdx.x, ty = threadIdx.y;
    int tid = ty * 16 + tx;
    int rb = blockIdx.y * 64, cb = blockIdx.x * 64;

    for (int i = tid; i < 64 * 64; i += 256) {
        int rr = i >> 6, kk = i & 63;
        xs[rr][kk] = x[(rb + rr) * DIM + kk];
        ys[rr][kk] = y[(cb + rr) * DIM + kk];
    }
    __syncthreads();

    float acc[4][4] = {};
    #pragma unroll
    for (int k = 0; k < 64; k++) {
        float xv[4], yv[4];
        #pragma unroll
        for (int i = 0; i < 4; i++) xv[i] = xs[ty + 16 * i][k];
        #pragma unroll
        for (int j = 0; j < 4; j++) yv[j] = ys[tx + 16 * j][k];
        #pragma unroll
        for (int i = 0; i < 4; i++)
            #pragma unroll
            for (int j = 0; j < 4; j++)
                acc[i][j] += xv[i] * yv[j];
    }

    #pragma unroll
    for (int i = 0; i < 4; i++) {
        int r = rb + ty + 16 * i;
        float xnr = g_xn[r];
        #pragma unroll
        for (int j = 0; j < 4; j++) {
            int c = cb + tx + 16 * j;
            g_D[(size_t)r * NN + c] = (xnr + g_yn[c] - 2.0f * acc[i][j]) * LOG2E;
        }
    }
}

// ---------------- reset progress flags ----------------
__global__ void init_kernel() {
    if (threadIdx.x < NBLK) g_prog[threadIdx.x] = 0;
}

// ---------------- DP wavefront: 4x4 wavefront-order tiles, 2 warps/SMSP ------
__device__ __forceinline__ int ld_acq(const int* p) {
    int v;
    asm volatile("ld.acquire.gpu.u32 %0, [%1];" : "=r"(v) : "l"(p) : "memory");
    return v;
}
__device__ __forceinline__ void st_rel(int* p, int v) {
    asm volatile("st.release.gpu.u32 [%0], %1;" :: "l"(p), "r"(v) : "memory");
}
__device__ __forceinline__ float ex2(float x) {
    float r; asm("ex2.approx.f32 %0, %1;" : "=f"(r) : "f"(x)); return r;
}
__device__ __forceinline__ float lg2(float x) {
    float r; asm("lg2.approx.f32 %0, %1;" : "=f"(r) : "f"(x)); return r;
}

// base-2 softmin cell, 3 MUFU: the min's exp term is exactly 1.
#define CELL(nv, u, d, l, cost) do {                                   \
    float p_ = fminf((u), (d));                                        \
    float q_ = fmaxf((u), (d));                                        \
    float m_ = fminf(p_, (l));                                         \
    float md_ = fmaxf(p_, fminf(q_, (l)));                             \
    float mx_ = fmaxf(q_, (l));                                        \
    float s_ = 1.0f + ex2(m_ - md_) + ex2(m_ - mx_);                   \
    (nv) = (cost) + m_ - lg2(s_);                                      \
} while (0)

__global__ void __launch_bounds__(32 * WPB, 1) dp_kernel(float* __restrict__ out) {
    __shared__ float topb[WPB][18];   // per-warp boundary window

    const int wid = threadIdx.x >> 5;
    const int L = threadIdx.x & 31;
    const int b = blockIdx.x * WPB + wid;        // band id (pipeline order)
    const int row0 = b * 128 + 4 * L;
    const float4* __restrict__ Dr0 = (const float4*)(g_D + (size_t)(row0 + 0) * NN);
    const float4* __restrict__ Dr1 = (const float4*)(g_D + (size_t)(row0 + 1) * NN);
    const float4* __restrict__ Dr2 = (const float4*)(g_D + (size_t)(row0 + 2) * NN);
    const float4* __restrict__ Dr3 = (const float4*)(g_D + (size_t)(row0 + 3) * NN);
    float* mybnd = g_bnd[b];
    const float* upbnd = (b > 0) ? g_bnd[b - 1] : (const float*)0;
    float* tb = topb[wid];

    float lft0 = INF_V, lft1 = INF_V, lft2 = INF_V, lft3 = INF_V; // right edge of prev tile
    float bot0 = INF_V, bot1 = INF_V, bot2 = INF_V, bot3 = INF_V; // bottom row of prev tile
    float dgv = INF_V;                                             // v[row0-1][4j-1]

    float4 c0 = __ldg(Dr0), c1 = __ldg(Dr1), c2 = __ldg(Dr2), c3 = __ldg(Dr3);

    const int TT = NTILE + 31;
    #pragma unroll 1
    for (int tau = 0; tau < TT; tau++) {
        const int j = tau - L;                    // this lane's tile-column

        // ---- stage boundary window every 4 tiles (R4 protocol, verbatim) ----
        if (b > 0 && tau < NTILE && (tau & 3) == 0) {
            if (L == 0) { while (ld_acq(&g_prog[b - 1]) < tau + 4) { } }
            __syncwarp();
            if (L < 17) {
                int col = 4 * tau - 1 + L;
                tb[L] = (col >= 0) ? __ldcg(&upbnd[col]) : INF_V;
            }
            __syncwarp();
        }

        // ---- prefetch next tile's costs ----
        int jn = j + 1; if (jn < 0) jn = 0; if (jn > NTILE - 1) jn = NTILE - 1;
        float4 p0 = __ldg(Dr0 + jn);
        float4 p1 = __ldg(Dr1 + jn);
        float4 p2 = __ldg(Dr2 + jn);
        float4 p3 = __ldg(Dr3 + jn);

        // ---- top handoff: neighbor's bottom row from previous step ----
        float t0 = __shfl_up_sync(0xffffffffu, bot0, 1);
        float t1 = __shfl_up_sync(0xffffffffu, bot1, 1);
        float t2 = __shfl_up_sync(0xffffffffu, bot2, 1);
        float t3 = __shfl_up_sync(0xffffffffu, bot3, 1);
        if (L == 0) {
            if (b == 0) {
                t0 = t1 = t2 = t3 = INF_V;
                dgv = (tau == 0) ? 0.0f : INF_V;
            } else {
                int p = (tau & 3) * 4;
                dgv = tb[p];
                t0 = tb[p + 1]; t1 = tb[p + 2];
                t2 = tb[p + 3]; t3 = tb[p + 4];
            }
        }
        if (j == 0 && L > 0) dgv = INF_V;         // diag of col 0 is dp[.][-1]

        if (j >= 0 && j < NTILE) {
            // 4x4 tile, cells emitted in anti-diagonal (wavefront) order.
            float V00, V01, V02, V03;
            float V10, V11, V12, V13;
            float V20, V21, V22, V23;
            float V30, V31, V32, V33;
            // rank 0
            CELL(V00, t0,  dgv,  lft0, c0.x);
            // rank 1
            CELL(V01, t1,  t0,   V00,  c0.y);
            CELL(V10, V00, lft0, lft1, c1.x);
            // rank 2
            CELL(V02, t2,  t1,   V01,  c0.z);
            CELL(V11, V01, V00,  V10,  c1.y);
            CELL(V20, V10, lft1, lft2, c2.x);
            // rank 3
            CELL(V03, t3,  t2,   V02,  c0.w);
            CELL(V12, V02, V01,  V11,  c1.z);
            CELL(V21, V11, V10,  V20,  c2.y);
            CELL(V30, V20, lft2, lft3, c3.x);
            // rank 4
            CELL(V13, V03, V02,  V12,  c1.w);
            CELL(V22, V12, V11,  V21,  c2.z);
            CELL(V31, V21, V20,  V30,  c3.y);
            // rank 5
            CELL(V23, V13, V12,  V22,  c2.w);
            CELL(V32, V22, V21,  V31,  c3.z);
            // rank 6
            CELL(V33, V23, V22,  V32,  c3.w);

            lft0 = V03; lft1 = V13; lft2 = V23; lft3 = V33;
            bot0 = V30; bot1 = V31; bot2 = V32; bot3 = V33;

            if (L == 31) {
                *(float4*)&mybnd[4 * j] = make_float4(bot0, bot1, bot2, bot3);
                if ((j & 3) == 3 && b < NBLK - 1)
                    st_rel(&g_prog[b], j + 1);   // release orders mybnd stores
            }
        }
        dgv = t3;                                 // diag for next tile = top[3]

        c0 = p0; c1 = p1; c2 = p2; c3 = p3;       // rotate cost buffers
    }

    if (b == NBLK - 1 && L == 31) out[0] = lft3 * LN2;   // dp[4096][4096]
}

extern "C" void kernel_launch(void* const* d_in, const int* in_sizes, int n_in,
                              void* d_out, int out_size) {
    const float* x = (const float*)d_in[0];
    const float* y = (const float*)d_in[1];
    float* out = (float*)d_out;

    norms_kernel<<<(2 * NN * 32) / 256, 256>>>(x, y);
    dim3 gD(NN / 64, NN / 64);
    dim3 bD(16, 16);
    dmat_kernel<<<gD, bD>>>(x, y);
    init_kernel<<<1, NBLK>>>();
    dp_kernel<<<NBLK / WPB, 32 * WPB>>>(out);
}